// round 14
// baseline (speedup 1.0000x reference)
#include <cuda_runtime.h>

// Problem constants (fixed by setup_inputs)
#define CC      4
#define HH      256
#define WW      256
#define EE      32
#define OO      32
#define NN      125                  // (256-7)/2+1
#define NQ      (NN * NN)            // 15625
#define DIST_SCALE 10.0f
#define W_THR   1e-7f
#define FULL    0xFFFFFFFFu

// ---------------------------------------------------------------------------
// Fused kernel, TWO queries per warp (interleaved for ILP/MLP).
//  p1: coalesced distances for both queries, 16 independent LDG.128 in flight
//  p2: two interleaved softmax shuffle-butterflies (fill each other's latency)
//  p3/p4: per-query row-grouped gather + vector scatter-add (shared geometry)
// ---------------------------------------------------------------------------
__global__ __launch_bounds__(256) void agg_scatter_kernel(
        const float* __restrict__ x,
        const float* __restrict__ xe,
        const float* __restrict__ ye,
        const int*   __restrict__ inds,
        float*       __restrict__ out) {
    const int lane = threadIdx.x & 31;
    const int wrp  = threadIdx.x >> 5;

    const int qra = blockIdx.x * 16 + wrp * 2;     // raw query ids
    const int qrb = qra + 1;
    const bool sta = (qra < NQ);                   // warp-uniform store gates
    const bool stb = (qrb < NQ);
    const int qa = sta ? qra : NQ - 1;             // clamped for loads
    const int qb = stb ? qrb : NQ - 1;

    // ---- p1: coalesced distances, both queries interleaved ----
    const int g  = lane >> 3;                      // candidate group in instr
    const int ch = lane & 7;                       // float4 chunk of row
    const float4 ya = reinterpret_cast<const float4*>(ye + qa * EE)[ch];
    const float4 yb = reinterpret_cast<const float4*>(ye + qb * EE)[ch];
    const int pa_l  = inds[qa * OO + lane];
    const int pb_lz = inds[qb * OO + lane];

    float a[8], b[8];
#pragma unroll
    for (int k = 0; k < 8; k++) {
        const int poa = __shfl_sync(FULL, pa_l,  k * 4 + g);
        const int pob = __shfl_sync(FULL, pb_lz, k * 4 + g);
        const float4 va = reinterpret_cast<const float4*>(xe + poa * EE)[ch];
        const float4 vb = reinterpret_cast<const float4*>(xe + pob * EE)[ch];
        {
            const float dx = va.x - ya.x, dy = va.y - ya.y;
            const float dz = va.z - ya.z, dw = va.w - ya.w;
            a[k] = dx * dx + dy * dy + dz * dz + dw * dw;
        }
        {
            const float dx = vb.x - yb.x, dy = vb.y - yb.y;
            const float dz = vb.z - yb.z, dw = vb.w - yb.w;
            b[k] = dx * dx + dy * dy + dz * dz + dw * dw;
        }
    }

    // split-exchange reduction (both queries interleaved)
#pragma unroll
    for (int i = 0; i < 4; i++) {
        const float sa = (lane & 4) ? a[i] : a[i + 4];
        const float ka = (lane & 4) ? a[i + 4] : a[i];
        a[i] = ka + __shfl_xor_sync(FULL, sa, 4);
        const float sb = (lane & 4) ? b[i] : b[i + 4];
        const float kb = (lane & 4) ? b[i + 4] : b[i];
        b[i] = kb + __shfl_xor_sync(FULL, sb, 4);
    }
#pragma unroll
    for (int i = 0; i < 2; i++) {
        const float sa = (lane & 2) ? a[i] : a[i + 2];
        const float ka = (lane & 2) ? a[i + 2] : a[i];
        a[i] = ka + __shfl_xor_sync(FULL, sa, 2);
        const float sb = (lane & 2) ? b[i] : b[i + 2];
        const float kb = (lane & 2) ? b[i + 2] : b[i];
        b[i] = kb + __shfl_xor_sync(FULL, sb, 2);
    }
    float d2a, d2b;
    {
        const float sa = (lane & 1) ? a[0] : a[1];
        const float ka = (lane & 1) ? a[1] : a[0];
        d2a = ka + __shfl_xor_sync(FULL, sa, 1);
        const float sb = (lane & 1) ? b[0] : b[1];
        const float kb = (lane & 1) ? b[1] : b[0];
        d2b = kb + __shfl_xor_sync(FULL, sb, 1);
    }

    // lane holds d2 of candidate o' = ch*4 + g; realign patch ids
    const int my_o = (lane & 7) * 4 + (lane >> 3);
    const int mpa = __shfl_sync(FULL, pa_l,  my_o);
    const int mpb = __shfl_sync(FULL, pb_lz, my_o);

    // hoisted gather bases
    const int pia = mpa / NN, pja = mpa - pia * NN;
    const int pba_l = pia * (2 * WW) + pja * 2;
    const int pib = mpb / NN, pjb = mpb - pib * NN;
    const int pbb_l = pib * (2 * WW) + pjb * 2;

    // ---- p2: two interleaved softmax butterflies ----
    float ma = d2a, mb = d2b;
#pragma unroll
    for (int off = 16; off; off >>= 1) {
        ma = fminf(ma, __shfl_xor_sync(FULL, ma, off));
        mb = fminf(mb, __shfl_xor_sync(FULL, mb, off));
    }
    const float eva = __expf(-DIST_SCALE * (d2a - ma));
    const float evb = __expf(-DIST_SCALE * (d2b - mb));
    float sa = eva, sb = evb;
#pragma unroll
    for (int off = 16; off; off >>= 1) {
        sa += __shfl_xor_sync(FULL, sa, off);
        sb += __shfl_xor_sync(FULL, sb, off);
    }
    const float wa = eva / sa;
    const float wb = evb / sb;

    const unsigned surva = __ballot_sync(FULL, wa >= W_THR);
    const unsigned survb = __ballot_sync(FULL, wb >= W_THR);

    // ---- shared lane geometry for p3/p4 ----
    const int row3 = lane >> 2;
    const int pair = lane & 3;
    int  offs[4];
    bool act [4];
#pragma unroll
    for (int t = 0; t < 4; t++) {
        const int row = t * 8 + row3;
        act[t]  = (row < 28);
        const int rc = act[t] ? row : 0;
        const int c  = rc / 7;
        const int r  = rc - c * 7;
        offs[t] = c * (HH * WW) + r * WW + pair * 2;
    }
    const bool p3e = (pair == 3);

    // ---- p3+p4 per query ----
    auto do_query = [&](unsigned surv, float w, int pb_lane, int qraw,
                        bool store) {
        const int ks = __popc(surv);
        float2 acc[4];
#pragma unroll
        for (int t = 0; t < 4; t++) acc[t] = make_float2(0.f, 0.f);

        for (int s = 0; s < ks; s++) {
            const int   lo = __fns(surv, 0, s + 1);
            const float ws = __shfl_sync(FULL, w,       lo);
            const int   pb = __shfl_sync(FULL, pb_lane, lo);
#pragma unroll
            for (int t = 0; t < 4; t++) {
                if (act[t]) {
                    const float2 v = *reinterpret_cast<const float2*>(
                        x + offs[t] + pb);         // s=7 over-read in-image
                    acc[t].x += ws * v.x;
                    acc[t].y += ws * v.y;
                }
            }
        }

        if (store) {                               // warp-uniform
            const int qi  = qraw / NN;
            const int qj  = qraw - qi * NN;
            const int pbq = qi * (2 * WW) + qj * 2;
#pragma unroll
            for (int t = 0; t < 4; t++) {
                if (act[t]) {
                    const float ay = p3e ? 0.f : acc[t].y;
                    float* dst = out + offs[t] + pbq;   // 8B-aligned
                    asm volatile("red.global.add.v2.f32 [%0], {%1, %2};"
                                 :: "l"(dst), "f"(acc[t].x), "f"(ay)
                                 : "memory");
                }
            }
        }
    };

    do_query(surva, wa, pba_l, qra, sta);
    do_query(survb, wb, pbb_l, qrb, stb);
}

// ---------------------------------------------------------------------------
extern "C" void kernel_launch(void* const* d_in, const int* in_sizes, int n_in,
                              void* d_out, int out_size) {
    const float* x    = (const float*)d_in[0];
    const float* xe   = (const float*)d_in[1];
    const float* ye   = (const float*)d_in[2];
    const int*   inds = (const int*)  d_in[3];
    float*       out  = (float*)d_out;
    (void)in_sizes; (void)n_in;

    cudaMemsetAsync(out, 0, (size_t)out_size * sizeof(float));
    agg_scatter_kernel<<<(NQ + 15) / 16, 256>>>(x, xe, ye, inds, out);
}

// round 17
// speedup vs baseline: 1.0186x; 1.0186x over previous
#include <cuda_runtime.h>

// Problem constants (fixed by setup_inputs)
#define CC      4
#define HH      256
#define WW      256
#define EE      32
#define OO      32
#define NN      125                  // (256-7)/2+1
#define NQ      (NN * NN)            // 15625
#define DIST_SCALE 10.0f
#define W_THR   1e-7f
#define FULL    0xFFFFFFFFu

#define SBW     24                   // smem buffer row stride (cols 0..21 used)

// ---------------------------------------------------------------------------
// Fused kernel: one query per warp, 8 warps/CTA; CTA = 8 consecutive-j queries
// of ONE patch row i  ->  footprints share a 28-row x 22-col output window.
//  p1: coalesced distances (8 lanes/candidate row, 4 candidates per LDG.128),
//      split-exchange reduction (R13, measured best)
//  p2: warp softmax + ballot threshold
//  p3: row-grouped survivor gather from x (4x LDG.64 per survivor)
//  p4: warp plain-stores acc into 1 of 4 smem buffers (disjoint addresses,
//      no atomics), one barrier, then ONE fused CTA scatter (red.v2) --
//      ~40 output line-touches per CTA instead of ~304.
// ---------------------------------------------------------------------------
__global__ __launch_bounds__(256) void agg_scatter_kernel(
        const float* __restrict__ x,
        const float* __restrict__ xe,
        const float* __restrict__ ye,
        const int*   __restrict__ inds,
        float*       __restrict__ out) {
    const int lane = threadIdx.x & 31;
    const int wrp  = threadIdx.x >> 5;
    const int jb   = blockIdx.x;                   // 0..15
    const int i    = blockIdx.y;                   // 0..124
    const int j    = jb * 8 + wrp;
    const bool valid = (j < NN);                   // warp-uniform

    __shared__ float s_buf[4][28][SBW];            // 10.5KB, zero-init

    // zero-init (float4: 4*28*24/4 = 672 vec4 slots)
    {
        float4* sb4 = reinterpret_cast<float4*>(&s_buf[0][0][0]);
#pragma unroll
        for (int t = threadIdx.x; t < 4 * 28 * SBW / 4; t += 256)
            sb4[t] = make_float4(0.f, 0.f, 0.f, 0.f);
    }
    __syncthreads();                               // zero-init visible to all
                                                   // before any p4a store

    // lane geometry (shared by p3 + smem store)
    const int row3 = lane >> 2;
    const int pair = lane & 3;
    int  offs[4];
    bool act [4];
    int  rows[4];
#pragma unroll
    for (int t = 0; t < 4; t++) {
        const int row = t * 8 + row3;
        act[t]  = (row < 28);
        const int rc = act[t] ? row : 0;
        const int c  = rc / 7;
        const int r  = rc - c * 7;
        offs[t] = c * (HH * WW) + r * WW + pair * 2;
        rows[t] = rc;
    }

    if (valid) {
        const int q = i * NN + j;

        // ---- p1: coalesced distances ----
        const int g  = lane >> 3;
        const int ch = lane & 7;
        const float4 y4 = reinterpret_cast<const float4*>(ye + q * EE)[ch];
        const int p_l   = inds[q * OO + lane];

        float a[8];
#pragma unroll
        for (int k = 0; k < 8; k++) {
            const int po = __shfl_sync(FULL, p_l, k * 4 + g);
            const float4 v = reinterpret_cast<const float4*>(xe + po * EE)[ch];
            const float dx = v.x - y4.x, dy = v.y - y4.y;
            const float dz = v.z - y4.z, dw = v.w - y4.w;
            a[k] = dx * dx + dy * dy + dz * dz + dw * dw;
        }

        // split-exchange reduction; lane ends with d2 of o' = ch*4 + g
#pragma unroll
        for (int t = 0; t < 4; t++) {
            const float send = (lane & 4) ? a[t] : a[t + 4];
            const float keep = (lane & 4) ? a[t + 4] : a[t];
            a[t] = keep + __shfl_xor_sync(FULL, send, 4);
        }
#pragma unroll
        for (int t = 0; t < 2; t++) {
            const float send = (lane & 2) ? a[t] : a[t + 2];
            const float keep = (lane & 2) ? a[t + 2] : a[t];
            a[t] = keep + __shfl_xor_sync(FULL, send, 2);
        }
        const float send1 = (lane & 1) ? a[0] : a[1];
        const float keep1 = (lane & 1) ? a[1] : a[0];
        const float d2 = keep1 + __shfl_xor_sync(FULL, send1, 1);

        const int my_o = (lane & 7) * 4 + (lane >> 3);
        const int my_p = __shfl_sync(FULL, p_l, my_o);
        const int pi = my_p / NN;
        const int pj = my_p - pi * NN;
        const int pb_l = pi * (2 * WW) + pj * 2;

        // ---- p2: softmax + threshold ----
        float m = d2;
#pragma unroll
        for (int off = 16; off; off >>= 1)
            m = fminf(m, __shfl_xor_sync(FULL, m, off));
        const float ev = __expf(-DIST_SCALE * (d2 - m));
        float sum = ev;
#pragma unroll
        for (int off = 16; off; off >>= 1)
            sum += __shfl_xor_sync(FULL, sum, off);
        const float w = ev / sum;

        const unsigned surv = __ballot_sync(FULL, w >= W_THR);
        const int ks = __popc(surv);

        // ---- p3: row-grouped survivor gather from x ----
        float2 acc[4];
#pragma unroll
        for (int t = 0; t < 4; t++) acc[t] = make_float2(0.f, 0.f);

        for (int s = 0; s < ks; s++) {
            const int   lo = __fns(surv, 0, s + 1);
            const float ws = __shfl_sync(FULL, w,    lo);
            const int   pb = __shfl_sync(FULL, pb_l, lo);
#pragma unroll
            for (int t = 0; t < 4; t++) {
                if (act[t]) {
                    const float2 v = *reinterpret_cast<const float2*>(
                        x + offs[t] + pb);         // s=7 over-read in-image
                    acc[t].x += ws * v.x;
                    acc[t].y += ws * v.y;
                }
            }
        }

        // ---- p4a: plain smem store into buffer (wrp&3) at col 2*wrp+2*pair
        // Single writer per (buffer,row,col): warps w / w+4 cover disjoint
        // columns; pair==3 .y slot (s=7) belongs only to this lane -> 0.
        {
            const int b  = wrp & 3;
            const int cb = 2 * wrp + 2 * pair;     // even -> 8B-aligned
#pragma unroll
            for (int t = 0; t < 4; t++) {
                if (act[t]) {
                    const float ay = (pair == 3) ? 0.f : acc[t].y;
                    *reinterpret_cast<float2*>(&s_buf[b][rows[t]][cb]) =
                        make_float2(acc[t].x, ay);
                }
            }
        }
    }

    __syncthreads();

    // ---- p4b: fused CTA scatter: 28 rows x 11 col-pairs = 308 red.v2 ----
    const int colg0 = 16 * jb;                     // global col of local col 0
#pragma unroll
    for (int idx = threadIdx.x; idx < 28 * 11; idx += 256) {
        const int rr = idx / 11;                   // 0..27 = c*7 + r
        const int cp = idx - rr * 11;              // 0..10 -> cols 2cp, 2cp+1
        const int gc = colg0 + 2 * cp;
        if (gc <= 254) {                           // gc=254 -> col255 adds 0
            const float2 v0 = *reinterpret_cast<const float2*>(&s_buf[0][rr][2 * cp]);
            const float2 v1 = *reinterpret_cast<const float2*>(&s_buf[1][rr][2 * cp]);
            const float2 v2 = *reinterpret_cast<const float2*>(&s_buf[2][rr][2 * cp]);
            const float2 v3 = *reinterpret_cast<const float2*>(&s_buf[3][rr][2 * cp]);
            const float vx = v0.x + v1.x + v2.x + v3.x;
            const float vy = v0.y + v1.y + v2.y + v3.y;
            const int c = rr / 7;
            const int r = rr - c * 7;
            float* dst = out + c * (HH * WW) + (2 * i + r) * WW + gc;
            asm volatile("red.global.add.v2.f32 [%0], {%1, %2};"
                         :: "l"(dst), "f"(vx), "f"(vy)
                         : "memory");
        }
    }
}

// ---------------------------------------------------------------------------
extern "C" void kernel_launch(void* const* d_in, const int* in_sizes, int n_in,
                              void* d_out, int out_size) {
    const float* x    = (const float*)d_in[0];
    const float* xe   = (const float*)d_in[1];
    const float* ye   = (const float*)d_in[2];
    const int*   inds = (const int*)  d_in[3];
    float*       out  = (float*)d_out;
    (void)in_sizes; (void)n_in;

    cudaMemsetAsync(out, 0, (size_t)out_size * sizeof(float));
    dim3 grid((NN + 7) / 8, NN);                   // (jb=16, i=125)
    agg_scatter_kernel<<<grid, 256>>>(x, xe, ye, inds, out);
}